// round 1
// baseline (speedup 1.0000x reference)
#include <cuda_runtime.h>
#include <cstddef>

#define NTOT 4096
#define HD   256
#define LEN  32
#define KOBS 32
#define VOBS 128
#define VC   32
#define NL   131072   // NTOT*LEN

// ---------------- scratch (static device memory; no allocation) ----------------
__device__ float g_Mobs[KOBS * VOBS * HD];       // [k][v][h]   4 MB
__device__ float g_Q[16 * VC * 64];              // [tap][v][o] 128 KB
__device__ int   g_tok[NL];                      // argmax tokens
__device__ float g_ypre[(size_t)NL * HD];        // pre-BN conv output [n][l][h] 134 MB
__device__ float g_bnsum[HD];
__device__ float g_bnsq[HD];
__device__ float g_bnscale[HD];
__device__ float g_bnshift[HD];
__device__ float g_xp[(size_t)LEN * 3 * NTOT * HD]; // [l][g][n][h] 402 MB
__device__ float g_h[2][(size_t)NTOT * HD];      // GRU hidden ping-pong

__device__ __forceinline__ float prelu_f(float x, float a) { return x >= 0.f ? x : a * x; }

// ---------------- zero init ----------------
__global__ void k_zero() {
    int i = blockIdx.x * blockDim.x + threadIdx.x;
    if (i < NTOT * HD) g_h[0][i] = 0.f;
    if (i < HD) { g_bnsum[i] = 0.f; g_bnsq[i] = 0.f; }
}

// ---------------- obs lookup table: M[k][v][h] = prelu(obs_emb[v]) @ obs_W[k*H:(k+1)*H, :] ----------------
__global__ void k_obsM(const float* __restrict__ obs_emb, const float* __restrict__ aemb_p,
                       const float* __restrict__ obs_W) {
    __shared__ float P[8 * HD];   // 8 vocab rows, prelu'd
    int k = blockIdx.y;
    int vbase = blockIdx.x * 8;
    int tid = threadIdx.x;
    float a = *aemb_p;
    for (int t = tid; t < 8 * HD; t += 256)
        P[t] = prelu_f(obs_emb[vbase * HD + t], a);
    __syncthreads();

    float acc[8];
#pragma unroll
    for (int v = 0; v < 8; v++) acc[v] = 0.f;
    const float* Wp = obs_W + (size_t)k * HD * HD + tid;  // rows k*256..k*256+255, col tid
    for (int i = 0; i < HD; i++) {
        float w = Wp[(size_t)i * HD];
#pragma unroll
        for (int v = 0; v < 8; v++) acc[v] += P[v * HD + i] * w;
    }
#pragma unroll
    for (int v = 0; v < 8; v++)
        g_Mobs[((size_t)k * VOBS + vbase + v) * HD + tid] = acc[v];
}

// ---------------- conv lookup tables: Q[tap][v][o] ----------------
__global__ void k_Q(const float* __restrict__ ce, const float* __restrict__ cap,
                    const float* __restrict__ cw1, const float* __restrict__ cw3,
                    const float* __restrict__ cw5, const float* __restrict__ cw7) {
    __shared__ float Pc[HD * VC];  // transposed [i][v]
    int tap = blockIdx.x, tid = threadIdx.x;
    float a = *cap;
    for (int t = tid; t < VC * HD; t += 256) {
        int v = t >> 8, i = t & 255;
        Pc[i * VC + v] = prelu_f(ce[t], a);
    }
    __syncthreads();

    int g, tt;
    if (tap == 0)       { g = 0; tt = 0; }
    else if (tap < 4)   { g = 1; tt = tap - 1; }
    else if (tap < 9)   { g = 2; tt = tap - 4; }
    else                { g = 3; tt = tap - 9; }
    int ks = 2 * g + 1;
    const float* w = (g == 0) ? cw1 : (g == 1) ? cw3 : (g == 2) ? cw5 : cw7;

    int idx = blockIdx.y * 256 + tid;  // 2048 (o,v) pairs over 8 y-blocks
    int o = idx >> 5, v = idx & 31;
    float acc = 0.f;
    for (int i = 0; i < HD; i++)
        acc += Pc[i * VC + v] * w[((size_t)o * HD + i) * ks + tt];  // w uniform per warp (broadcast)
    g_Q[(tap * VC + v) * 64 + o] = acc;
}

// ---------------- token argmax (first-index tie break) ----------------
__global__ void k_tok(const float* __restrict__ comm) {
    int warp = (blockIdx.x * blockDim.x + threadIdx.x) >> 5;
    int lane = threadIdx.x & 31;
    if (warp >= NL) return;
    float v = comm[(size_t)warp * VC + lane];
    int idx = lane;
#pragma unroll
    for (int off = 16; off; off >>= 1) {
        float ov = __shfl_xor_sync(0xffffffffu, v, off);
        int   oi = __shfl_xor_sync(0xffffffffu, idx, off);
        if (ov > v || (ov == v && oi < idx)) { v = ov; idx = oi; }
    }
    if (lane == 0) g_tok[warp] = idx;
}

// ---------------- obs output half: gather-sum of M + prelu ----------------
__global__ void k_obsOut(const float* __restrict__ obs, const float* __restrict__ obs_b,
                         const float* __restrict__ obs_a_p, float* __restrict__ out) {
    __shared__ int sidx[KOBS];
    __shared__ int wcnt[8];
    int n = blockIdx.x, tid = threadIdx.x;
    int flag = 0;
    if (tid < VOBS) flag = obs[(size_t)n * VOBS + tid] > 0.5f;
    unsigned mask = __ballot_sync(0xffffffffu, flag);
    int lane = tid & 31, w = tid >> 5;
    if (lane == 0) wcnt[w] = __popc(mask);
    __syncthreads();
    if (flag) {
        int base = 0;
        for (int j = 0; j < w; j++) base += wcnt[j];
        sidx[base + __popc(mask & ((1u << lane) - 1u))] = tid;
    }
    __syncthreads();

    float acc = obs_b[tid];
#pragma unroll 8
    for (int k = 0; k < KOBS; k++)
        acc += g_Mobs[((size_t)k * VOBS + sidx[k]) * HD + tid];
    out[(size_t)n * (2 * HD) + tid] = prelu_f(acc, *obs_a_p);
}

// ---------------- conv-as-lookup -> y_pre + BN partial sums ----------------
__global__ void k_ypre(const float* __restrict__ cb1, const float* __restrict__ cb3,
                       const float* __restrict__ cb5, const float* __restrict__ cb7) {
    __shared__ int tk[LEN];
    int n = blockIdx.x, tid = threadIdx.x;
    if (tid < LEN) tk[tid] = g_tok[n * LEN + tid];
    __syncthreads();

    int g = tid >> 6, o = tid & 63;
    int ks = 2 * g + 1, pad = g, base = g * g;   // tap bases: 0,1,4,9
    const float* cbp = (g == 0) ? cb1 : (g == 1) ? cb3 : (g == 2) ? cb5 : cb7;
    float bias = cbp[o];

    float ls = 0.f, lq = 0.f;
    for (int l = 0; l < LEN; l++) {
        float acc = bias;
        for (int t = 0; t < ks; t++) {
            int lp = l + t - pad;
            if (lp >= 0 && lp < LEN)
                acc += g_Q[((base + t) * VC + tk[lp]) * 64 + o];
        }
        g_ypre[((size_t)n * LEN + l) * HD + tid] = acc;
        ls += acc; lq += acc * acc;
    }
    atomicAdd(&g_bnsum[tid], ls);
    atomicAdd(&g_bnsq[tid], lq);
}

// ---------------- BN finalize ----------------
__global__ void k_bnfin(const float* __restrict__ bn_g, const float* __restrict__ bn_b) {
    int h = threadIdx.x;
    float m   = g_bnsum[h] * (1.0f / 131072.0f);
    float var = g_bnsq[h]  * (1.0f / 131072.0f) - m * m;
    float sc  = bn_g[h] * rsqrtf(var + 1e-5f);
    g_bnscale[h] = sc;
    g_bnshift[h] = bn_b[h] - m * sc;
}

// ---------------- xproj GEMM: A=[131072,256] (BN+prelu on the fly) x B=[256,768] ----------------
__global__ void k_xproj(const float* __restrict__ Wx, const float* __restrict__ bx,
                        const float* __restrict__ cnn_a_p) {
    __shared__ __align__(16) float As[128][33];
    __shared__ __align__(16) float Bs[32][64];
    float ca = *cnn_a_p;
    int tid = threadIdx.x;
    int rowbase = blockIdx.x * 128;
    int gsel = blockIdx.y >> 2;
    int kbase = (blockIdx.y & 3) * 64;
    int tx = tid & 15, ty = tid >> 4;   // 16x4 cols, 16x8 rows

    float acc[8][4];
#pragma unroll
    for (int j = 0; j < 8; j++)
#pragma unroll
        for (int u = 0; u < 4; u++) acc[j][u] = 0.f;

    for (int i0 = 0; i0 < HD; i0 += 32) {
        for (int t = tid; t < 128 * 32; t += 256) {
            int kk = t & 31, r = t >> 5;
            int ch = i0 + kk;
            float v = g_ypre[(size_t)(rowbase + r) * HD + ch];
            v = prelu_f(v * g_bnscale[ch] + g_bnshift[ch], ca);
            As[r][kk] = v;
        }
        for (int t = tid; t < 32 * 64; t += 256) {
            int c = t & 63, kk = t >> 6;
            Bs[kk][c] = Wx[((size_t)gsel * HD + i0 + kk) * HD + kbase + c];
        }
        __syncthreads();
#pragma unroll
        for (int kk = 0; kk < 32; kk++) {
            float a[8];
#pragma unroll
            for (int j = 0; j < 8; j++) a[j] = As[ty * 8 + j][kk];
            float4 b = *(const float4*)&Bs[kk][tx * 4];
#pragma unroll
            for (int j = 0; j < 8; j++) {
                acc[j][0] += a[j] * b.x; acc[j][1] += a[j] * b.y;
                acc[j][2] += a[j] * b.z; acc[j][3] += a[j] * b.w;
            }
        }
        __syncthreads();
    }
#pragma unroll
    for (int j = 0; j < 8; j++) {
        int row = rowbase + ty * 8 + j;
        int n = row >> 5, l = row & 31;
#pragma unroll
        for (int u = 0; u < 4; u++) {
            int k = kbase + tx * 4 + u;
            g_xp[(((size_t)l * 3 + gsel) * NTOT + n) * HD + k] = acc[j][u] + bx[gsel * HD + k];
        }
    }
}

// ---------------- GRU step: fused h@Wh (3 gates) + gate math, ping-pong h ----------------
__global__ void k_gru(const float* __restrict__ Wh, const float* __restrict__ bh,
                      int l, int cur) {
    __shared__ __align__(16) float As[32][33];
    __shared__ __align__(16) float Bs[32][192];
    int tid = threadIdx.x;
    int rowbase = blockIdx.x * 32;
    int htile = blockIdx.y * 64;
    int tx = tid & 31, ty = tid >> 5;   // tx: 32 h-pairs, ty: 8 row-groups of 4
    const float* hcur = g_h[cur];

    float acc[4][2][3];
#pragma unroll
    for (int j = 0; j < 4; j++)
#pragma unroll
        for (int u = 0; u < 2; u++)
#pragma unroll
            for (int g = 0; g < 3; g++) acc[j][u][g] = 0.f;

    for (int i0 = 0; i0 < HD; i0 += 32) {
        for (int t = tid; t < 32 * 32; t += 256) {
            int kk = t & 31, r = t >> 5;
            As[r][kk] = hcur[(size_t)(rowbase + r) * HD + i0 + kk];
        }
        for (int t = tid; t < 32 * 192; t += 256) {
            int c = t % 192, kk = t / 192;
            int g = c >> 6, hh = c & 63;
            Bs[kk][c] = Wh[((size_t)g * HD + i0 + kk) * HD + htile + hh];
        }
        __syncthreads();
#pragma unroll
        for (int kk = 0; kk < 32; kk++) {
            float a[4];
#pragma unroll
            for (int j = 0; j < 4; j++) a[j] = As[ty * 4 + j][kk];
#pragma unroll
            for (int g = 0; g < 3; g++) {
                float2 b = *(const float2*)&Bs[kk][g * 64 + tx * 2];
#pragma unroll
                for (int j = 0; j < 4; j++) {
                    acc[j][0][g] += a[j] * b.x;
                    acc[j][1][g] += a[j] * b.y;
                }
            }
        }
        __syncthreads();
    }

    int nxt = cur ^ 1;
#pragma unroll
    for (int j = 0; j < 4; j++) {
        int row = rowbase + ty * 4 + j;
#pragma unroll
        for (int u = 0; u < 2; u++) {
            int h = htile + tx * 2 + u;
            float hr = acc[j][u][0] + bh[h];
            float hz = acc[j][u][1] + bh[HD + h];
            float hn = acc[j][u][2] + bh[2 * HD + h];
            size_t xb = (((size_t)l * 3) * NTOT + row) * HD + h;
            float xr = g_xp[xb];
            float xz = g_xp[xb + (size_t)NTOT * HD];
            float xn = g_xp[xb + 2 * (size_t)NTOT * HD];
            float r  = 1.f / (1.f + __expf(-(xr + hr)));
            float z  = 1.f / (1.f + __expf(-(xz + hz)));
            float nn = tanhf(xn + r * hn);
            float ho = hcur[(size_t)row * HD + h];
            g_h[nxt][(size_t)row * HD + h] = nn * (1.f - z) + ho * z;
        }
    }
}

// ---------------- final linear: prelu(prelu(h)@W + b) -> out[:,256:512] ----------------
__global__ void k_final(const float* __restrict__ linW, const float* __restrict__ linb,
                        const float* __restrict__ a1p, const float* __restrict__ a2p,
                        float* __restrict__ out) {
    __shared__ __align__(16) float As[64][33];
    __shared__ __align__(16) float Bs[32][64];
    float a1 = *a1p, a2 = *a2p;
    int tid = threadIdx.x;
    int rowbase = blockIdx.x * 64, cbase = blockIdx.y * 64;
    int tx = tid & 15, ty = tid >> 4;

    float acc[4][4];
#pragma unroll
    for (int j = 0; j < 4; j++)
#pragma unroll
        for (int u = 0; u < 4; u++) acc[j][u] = 0.f;

    for (int i0 = 0; i0 < HD; i0 += 32) {
        for (int t = tid; t < 64 * 32; t += 256) {
            int kk = t & 31, r = t >> 5;
            As[r][kk] = prelu_f(g_h[0][(size_t)(rowbase + r) * HD + i0 + kk], a1);
        }
        for (int t = tid; t < 32 * 64; t += 256) {
            int c = t & 63, kk = t >> 6;
            Bs[kk][c] = linW[(size_t)(i0 + kk) * HD + cbase + c];
        }
        __syncthreads();
#pragma unroll
        for (int kk = 0; kk < 32; kk++) {
            float a[4];
#pragma unroll
            for (int j = 0; j < 4; j++) a[j] = As[ty * 4 + j][kk];
            float4 b = *(const float4*)&Bs[kk][tx * 4];
#pragma unroll
            for (int j = 0; j < 4; j++) {
                acc[j][0] += a[j] * b.x; acc[j][1] += a[j] * b.y;
                acc[j][2] += a[j] * b.z; acc[j][3] += a[j] * b.w;
            }
        }
        __syncthreads();
    }
#pragma unroll
    for (int j = 0; j < 4; j++) {
        int row = rowbase + ty * 4 + j;
#pragma unroll
        for (int u = 0; u < 4; u++) {
            int c = cbase + tx * 4 + u;
            out[(size_t)row * 512 + 256 + c] = prelu_f(acc[j][u] + linb[c], a2);
        }
    }
}

// ---------------- launch ----------------
extern "C" void kernel_launch(void* const* d_in, const int* in_sizes, int n_in,
                              void* d_out, int out_size) {
    (void)in_sizes; (void)n_in; (void)out_size;
    const float* obs        = (const float*)d_in[0];
    const float* comm       = (const float*)d_in[1];
    const float* obs_emb    = (const float*)d_in[2];
    const float* obs_a_emb  = (const float*)d_in[3];
    const float* obs_W      = (const float*)d_in[4];
    const float* obs_b      = (const float*)d_in[5];
    const float* obs_a      = (const float*)d_in[6];
    const float* comm_emb   = (const float*)d_in[7];
    const float* comm_a_emb = (const float*)d_in[8];
    const float* cw1 = (const float*)d_in[9];
    const float* cb1 = (const float*)d_in[10];
    const float* cw3 = (const float*)d_in[11];
    const float* cb3 = (const float*)d_in[12];
    const float* cw5 = (const float*)d_in[13];
    const float* cb5 = (const float*)d_in[14];
    const float* cw7 = (const float*)d_in[15];
    const float* cb7 = (const float*)d_in[16];
    const float* bn_g  = (const float*)d_in[17];
    const float* bn_b  = (const float*)d_in[18];
    const float* cnn_a = (const float*)d_in[19];
    const float* Wx = (const float*)d_in[20];
    const float* bx = (const float*)d_in[21];
    const float* Wh = (const float*)d_in[22];
    const float* bh = (const float*)d_in[23];
    const float* lin_a1 = (const float*)d_in[24];
    const float* lin_W  = (const float*)d_in[25];
    const float* lin_b  = (const float*)d_in[26];
    const float* lin_a2 = (const float*)d_in[27];
    float* out = (float*)d_out;

    k_zero<<<2048, 512>>>();
    k_obsM<<<dim3(16, 32), 256>>>(obs_emb, obs_a_emb, obs_W);
    k_Q<<<dim3(16, 8), 256>>>(comm_emb, comm_a_emb, cw1, cw3, cw5, cw7);
    k_tok<<<32768, 128>>>(comm);
    k_obsOut<<<4096, 256>>>(obs, obs_b, obs_a, out);
    k_ypre<<<4096, 256>>>(cb1, cb3, cb5, cb7);
    k_bnfin<<<1, 256>>>(bn_g, bn_b);
    k_xproj<<<dim3(1024, 12), 256>>>(Wx, bx, cnn_a);
    for (int l = 0; l < LEN; l++)
        k_gru<<<dim3(128, 4), 256>>>(Wh, bh, l, l & 1);
    k_final<<<dim3(64, 4), 256>>>(lin_W, lin_b, lin_a1, lin_a2, out);
}